// round 5
// baseline (speedup 1.0000x reference)
#include <cuda_runtime.h>
#include <math.h>

// Problem constants (reference hardcodes H=W=512, N=4096).
#define NG     4096
#define HIMG   512
#define WIMG   512
#define HW     (HIMG * WIMG)
#define TILE   8
#define TXN    (WIMG / TILE)   // 64
#define TYN    (HIMG / TILE)   // 64
#define NTILES (TXN * TYN)     // 4096
#define CAP    1024
#define NB     1024            // blocks (single co-resident wave, guaranteed)
#define NT     128             // threads per block

// Static device scratch (zero-initialized at load; kernel restores zeros
// before exit so every graph replay sees identical initial state).
__device__ float4 g_pa[NG];                 // px, py, 0.5*c0, c1
__device__ float4 g_pb[NG];                 // 0.5*c2, feat_r, feat_g, feat_b
__device__ float4 g_pc[NG];                 // geo_r, geo_g, geo_b, unused
__device__ int    g_tile_cnt[NTILES];
__device__ int    g_tile_list[NTILES * CAP];
__device__ int    g_arrive;                 // grid barrier arrive counter
__device__ int    g_done;                   // exit counter (last block resets)

__global__ __launch_bounds__(NT, 9)
void fused_kernel(const float* __restrict__ xyz,
                  const float* __restrict__ chol,
                  const float* __restrict__ feat,
                  const float* __restrict__ rcol,
                  float* __restrict__ out) {
    int b   = blockIdx.x;
    int tid = threadIdx.x;

    // ---------------- Phase A: project + bin (4 gaussians per block) -------
    if (tid < 4) {
        int i = b * 4 + tid;   // exactly NG = NB*4

        out[7 * HW + i] = 1.0f;  // opac output = ones(N,1)

        float mx = tanhf(xyz[2 * i + 0]);
        float my = tanhf(xyz[2 * i + 1]);

        float l0 = chol[3 * i + 0] + 0.5f;
        float l1 = chol[3 * i + 1];
        float l2 = chol[3 * i + 2] + 0.5f;

        float s00 = l0 * l0;
        float s01 = l0 * l1;
        float s11 = l1 * l1 + l2 * l2;
        float det = s00 * s11 - s01 * s01;
        float inv = 1.0f / det;
        float c0 =  s11 * inv;
        float c1 = -s01 * inv;
        float c2 =  s00 * inv;

        float px = 0.5f * ((mx + 1.0f) * (float)WIMG - 1.0f);
        float py = 0.5f * ((my + 1.0f) * (float)HIMG - 1.0f);

        g_pa[i] = make_float4(px, py, 0.5f * c0, c1);
        g_pb[i] = make_float4(0.5f * c2, feat[3 * i], feat[3 * i + 1], feat[3 * i + 2]);
        g_pc[i] = make_float4(0.5f * rcol[3 * i], 0.5f * rcol[3 * i + 1],
                              0.5f * rcol[3 * i + 2], 0.0f);

        // Conservative bbox: live requires sigma <= ln(255) ~ 5.5413.
        const float T = 5.65f;
        float hx = sqrtf(2.0f * T * s00) + 1.0f;
        float hy = sqrtf(2.0f * T * s11) + 1.0f;

        if (!(px + hx < 0.0f || px - hx > (float)(WIMG - 1) ||
              py + hy < 0.0f || py - hy > (float)(HIMG - 1))) {
            int x0 = max(0,       (int)floorf((px - hx) * (1.0f / TILE)));
            int x1 = min(TXN - 1, (int)floorf((px + hx) * (1.0f / TILE)));
            int y0 = max(0,       (int)floorf((py - hy) * (1.0f / TILE)));
            int y1 = min(TYN - 1, (int)floorf((py + hy) * (1.0f / TILE)));
            for (int ty = y0; ty <= y1; ty++) {
                for (int tx = x0; tx <= x1; tx++) {
                    int t = ty * TXN + tx;
                    int slot = atomicAdd(&g_tile_cnt[t], 1);
                    if (slot < CAP) g_tile_list[t * CAP + slot] = i;
                }
            }
        }
    }

    // ---------------- Grid barrier (all NB blocks are co-resident) ---------
    __threadfence();
    __syncthreads();
    if (tid == 0) {
        atomicAdd(&g_arrive, 1);
        while (atomicAdd(&g_arrive, 0) < NB) __nanosleep(32);
    }
    __syncthreads();
    __threadfence();

    // ---------------- Phase B: raster 4 tiles per block --------------------
    __shared__ float4 sa[NT];
    __shared__ float4 sb[NT];
    __shared__ float4 sc[NT];
    __shared__ float  s_part[64][8];   // partial accums from group 1

    int grp = tid >> 6;        // 0 or 1: gaussian-list parity group
    int px_ = tid & 63;        // pixel within 8x8 tile
    int lx  = px_ & 7;
    int ly  = px_ >> 3;

    for (int tt = 0; tt < 4; tt++) {
        int tile  = b + tt * NB;
        int tilex = tile & (TXN - 1);
        int tiley = tile >> 6;

        int   pxi = tilex * TILE + lx;
        int   pyi = tiley * TILE + ly;
        float pxf = (float)pxi;
        float pyf = (float)pyi;

        int cnt = g_tile_cnt[tile];
        if (cnt > CAP) cnt = CAP;

        float ar = 0.f, ag = 0.f, ab = 0.f;
        float gr = 0.f, gg = 0.f, gb = 0.f;
        float aa = 0.f;

        for (int base = 0; base < cnt; base += NT) {
            int n = min(NT, cnt - base);
            __syncthreads();
            if (tid < n) {
                int id = g_tile_list[tile * CAP + base + tid];
                sa[tid] = g_pa[id];
                sb[tid] = g_pb[id];
                sc[tid] = g_pc[id];
            }
            __syncthreads();
            for (int j = grp; j < n; j += 2) {
                float4 a = sa[j];
                float dx = a.x - pxf;
                float dy = a.y - pyf;
                float c2h = sb[j].x;
                float sigma = fmaf(dx, fmaf(a.z, dx, a.w * dy), c2h * dy * dy);
                float e = __expf(-sigma);
                bool live = (sigma >= 0.0f) && (e >= (1.0f / 255.0f));
                float alpha = live ? fminf(0.999f, e) : 0.0f;
                float4 bb = sb[j];
                float4 cc = sc[j];
                ar += alpha * bb.y;
                ag += alpha * bb.z;
                ab += alpha * bb.w;
                gr += alpha * cc.x;
                gg += alpha * cc.y;
                gb += alpha * cc.z;
                aa += alpha;
            }
        }

        __syncthreads();           // protect s_part reuse across tiles
        if (grp == 1) {
            s_part[px_][0] = ar; s_part[px_][1] = ag; s_part[px_][2] = ab;
            s_part[px_][3] = gr; s_part[px_][4] = gg; s_part[px_][5] = gb;
            s_part[px_][6] = aa;
        }
        __syncthreads();
        if (grp == 0) {
            ar += s_part[px_][0]; ag += s_part[px_][1]; ab += s_part[px_][2];
            gr += s_part[px_][3]; gg += s_part[px_][4]; gb += s_part[px_][5];
            aa += s_part[px_][6];
            int pix = pyi * WIMG + pxi;
            out[0 * HW + pix] = fminf(1.0f, fmaxf(0.0f, ar));
            out[1 * HW + pix] = fminf(1.0f, fmaxf(0.0f, ag));
            out[2 * HW + pix] = fminf(1.0f, fmaxf(0.0f, ab));
            out[3 * HW + pix] = fminf(1.0f, fmaxf(0.0f, gr));
            out[4 * HW + pix] = fminf(1.0f, fmaxf(0.0f, gg));
            out[5 * HW + pix] = fminf(1.0f, fmaxf(0.0f, gb));
            out[6 * HW + pix] = aa;
        }
        if (tid == 0) g_tile_cnt[tile] = 0;   // restore zero state
    }

    // ---------------- Exit: last block resets barrier counters -------------
    __syncthreads();
    if (tid == 0) {
        int d = atomicAdd(&g_done, 1);
        if (d == NB - 1) {
            g_arrive = 0;
            g_done   = 0;
            __threadfence();
        }
    }
}

extern "C" void kernel_launch(void* const* d_in, const int* in_sizes, int n_in,
                              void* d_out, int out_size) {
    const float* xyz  = (const float*)d_in[0];
    const float* chol = (const float*)d_in[1];
    const float* feat = (const float*)d_in[2];
    const float* rcol = (const float*)d_in[3];
    float* out = (float*)d_out;

    fused_kernel<<<NB, NT>>>(xyz, chol, feat, rcol, out);
}

// round 6
// speedup vs baseline: 1.2448x; 1.2448x over previous
#include <cuda_runtime.h>
#include <math.h>

// Problem constants (reference hardcodes H=W=512, N=4096).
#define NG     4096
#define HIMG   512
#define WIMG   512
#define HW     (HIMG * WIMG)
#define TW     16
#define TH     8
#define TXN    (WIMG / TW)     // 32 tiles in x
#define TYN    (HIMG / TH)     // 64 tiles in y
#define NTILES (TXN * TYN)     // 2048
#define CAP    512
#define NB     1024            // blocks: single co-resident wave (<=7/SM needed, 8 guaranteed)
#define NT     128             // threads per block

// Static device scratch (zero-initialized at load; kernel restores zeros
// before exit so every graph replay sees identical initial state).
__device__ float4 g_pa[NG];                 // px, py, 0.5*c0, c1
__device__ float4 g_pb[NG];                 // 0.5*c2, feat_r, feat_g, feat_b
__device__ float4 g_pc[NG];                 // geo_r, geo_g, geo_b, unused
__device__ int    g_tile_cnt[NTILES];
__device__ int    g_tile_list[NTILES * CAP];
__device__ int    g_arrive;                 // grid barrier arrive counter
__device__ int    g_done;                   // exit counter (last block resets)

__global__ __launch_bounds__(NT, 8)
void fused_kernel(const float* __restrict__ xyz,
                  const float* __restrict__ chol,
                  const float* __restrict__ feat,
                  const float* __restrict__ rcol,
                  float* __restrict__ out) {
    int b   = blockIdx.x;
    int tid = threadIdx.x;

    // ---------------- Phase A: project + bin (4 gaussians per block) -------
    if (tid < 4) {
        int i = b * 4 + tid;   // exactly NG = NB*4

        out[7 * HW + i] = 1.0f;  // opac output = ones(N,1)

        float mx = tanhf(xyz[2 * i + 0]);
        float my = tanhf(xyz[2 * i + 1]);

        float l0 = chol[3 * i + 0] + 0.5f;
        float l1 = chol[3 * i + 1];
        float l2 = chol[3 * i + 2] + 0.5f;

        float s00 = l0 * l0;
        float s01 = l0 * l1;
        float s11 = l1 * l1 + l2 * l2;
        float det = s00 * s11 - s01 * s01;
        float inv = 1.0f / det;
        float c0 =  s11 * inv;
        float c1 = -s01 * inv;
        float c2 =  s00 * inv;

        float px = 0.5f * ((mx + 1.0f) * (float)WIMG - 1.0f);
        float py = 0.5f * ((my + 1.0f) * (float)HIMG - 1.0f);

        g_pa[i] = make_float4(px, py, 0.5f * c0, c1);
        g_pb[i] = make_float4(0.5f * c2, feat[3 * i], feat[3 * i + 1], feat[3 * i + 2]);
        g_pc[i] = make_float4(0.5f * rcol[3 * i], 0.5f * rcol[3 * i + 1],
                              0.5f * rcol[3 * i + 2], 0.0f);

        // Exact extents: live requires sigma <= ln(255) = 5.5413 (+eps).
        const float T = 5.545f;
        float hx = sqrtf(2.0f * T * s00);
        float hy = sqrtf(2.0f * T * s11);

        // Tiles tx with pixel range [TW*tx, TW*tx+TW-1] intersecting [px-hx, px+hx].
        int x0 = max(0,       (int)ceilf ((px - hx - (float)(TW - 1)) * (1.0f / TW)));
        int x1 = min(TXN - 1, (int)floorf((px + hx) * (1.0f / TW)));
        int y0 = max(0,       (int)ceilf ((py - hy - (float)(TH - 1)) * (1.0f / TH)));
        int y1 = min(TYN - 1, (int)floorf((py + hy) * (1.0f / TH)));

        for (int ty = y0; ty <= y1; ty++) {
            for (int tx = x0; tx <= x1; tx++) {
                int t = ty * TXN + tx;
                int slot = atomicAdd(&g_tile_cnt[t], 1);
                if (slot < CAP) g_tile_list[t * CAP + slot] = i;
            }
        }
    }

    // ---------------- Grid barrier: arrive once, poll with plain loads -----
    __threadfence();               // publish phase-A stores before arrival
    __syncthreads();
    if (tid == 0) {
        atomicAdd(&g_arrive, 1);
        volatile int* p = &g_arrive;
        while (*p < NB) __nanosleep(256);
    }
    __syncthreads();
    __threadfence();               // acquire: order phase-B loads after poll

    // ---------------- Phase B: raster 2 tiles (16x8 px) per block ----------
    __shared__ float4 sa[NT];
    __shared__ float4 sb[NT];
    __shared__ float4 sc[NT];

    int lx = tid & (TW - 1);
    int ly = tid >> 4;              // 0..7

    for (int tt = 0; tt < 2; tt++) {
        int tile  = b + tt * NB;
        int tilex = tile & (TXN - 1);
        int tiley = tile >> 5;      // tile / TXN

        int   pxi = tilex * TW + lx;
        int   pyi = tiley * TH + ly;
        float pxf = (float)pxi;
        float pyf = (float)pyi;

        int cnt = g_tile_cnt[tile];
        if (cnt > CAP) cnt = CAP;

        float ar = 0.f, ag = 0.f, ab = 0.f;
        float gr = 0.f, gg = 0.f, gb = 0.f;
        float aa = 0.f;

        for (int base = 0; base < cnt; base += NT) {
            int n = min(NT, cnt - base);
            __syncthreads();
            if (tid < n) {
                int id = g_tile_list[tile * CAP + base + tid];
                sa[tid] = g_pa[id];
                sb[tid] = g_pb[id];
                sc[tid] = g_pc[id];
            }
            __syncthreads();
            #pragma unroll 2
            for (int j = 0; j < n; j++) {
                float4 a = sa[j];
                float dx = a.x - pxf;
                float dy = a.y - pyf;
                float c2h = sb[j].x;
                float sigma = fmaf(dx, fmaf(a.z, dx, a.w * dy), c2h * dy * dy);
                float e = __expf(-sigma);
                bool live = (sigma >= 0.0f) && (e >= (1.0f / 255.0f));
                float alpha = live ? fminf(0.999f, e) : 0.0f;
                float4 bb = sb[j];
                float4 cc = sc[j];
                ar += alpha * bb.y;
                ag += alpha * bb.z;
                ab += alpha * bb.w;
                gr += alpha * cc.x;
                gg += alpha * cc.y;
                gb += alpha * cc.z;
                aa += alpha;
            }
        }

        int pix = pyi * WIMG + pxi;
        out[0 * HW + pix] = fminf(1.0f, fmaxf(0.0f, ar));
        out[1 * HW + pix] = fminf(1.0f, fmaxf(0.0f, ag));
        out[2 * HW + pix] = fminf(1.0f, fmaxf(0.0f, ab));
        out[3 * HW + pix] = fminf(1.0f, fmaxf(0.0f, gr));
        out[4 * HW + pix] = fminf(1.0f, fmaxf(0.0f, gg));
        out[5 * HW + pix] = fminf(1.0f, fmaxf(0.0f, gb));
        out[6 * HW + pix] = aa;

        if (tid == 0) g_tile_cnt[tile] = 0;   // restore zero state
        __syncthreads();                       // keep smem reuse safe
    }

    // ---------------- Exit: last block resets barrier counters -------------
    if (tid == 0) {
        int d = atomicAdd(&g_done, 1);
        if (d == NB - 1) {
            g_arrive = 0;
            g_done   = 0;
            __threadfence();
        }
    }
}

extern "C" void kernel_launch(void* const* d_in, const int* in_sizes, int n_in,
                              void* d_out, int out_size) {
    const float* xyz  = (const float*)d_in[0];
    const float* chol = (const float*)d_in[1];
    const float* feat = (const float*)d_in[2];
    const float* rcol = (const float*)d_in[3];
    float* out = (float*)d_out;

    fused_kernel<<<NB, NT>>>(xyz, chol, feat, rcol, out);
}

// round 7
// speedup vs baseline: 1.2519x; 1.0057x over previous
#include <cuda_runtime.h>
#include <math.h>

// Problem constants (reference hardcodes H=W=512, N=4096).
#define NG     4096
#define HIMG   512
#define WIMG   512
#define HW     (HIMG * WIMG)
#define TW     16
#define TH     8
#define TXN    (WIMG / TW)     // 32 tiles in x
#define TYN    (HIMG / TH)     // 64 tiles in y
#define NTILES (TXN * TYN)     // 2048
#define CAP    128             // per-tile capacity (observed max ~13-25)
#define NB     1024            // blocks: proven single co-resident wave
#define NT     128             // threads per block

// Static device scratch (zero-initialized at load; kernel restores zeros
// before exit so every graph replay sees identical initial state).
// Payload-direct tile lists: no index indirection in the raster phase.
__device__ float4 g_la[NTILES * CAP];       // px, py, 0.5*c0, c1
__device__ float4 g_lb[NTILES * CAP];       // 0.5*c2, feat_r, feat_g, feat_b
__device__ float4 g_lc[NTILES * CAP];       // geo_r, geo_g, geo_b, unused
__device__ int    g_tile_cnt[NTILES];
__device__ int    g_arrive;                 // grid barrier arrive counter
__device__ int    g_done;                   // exit counter (last block resets)

__global__ __launch_bounds__(NT, 8)
void fused_kernel(const float* __restrict__ xyz,
                  const float* __restrict__ chol,
                  const float* __restrict__ feat,
                  const float* __restrict__ rcol,
                  float* __restrict__ out) {
    int b   = blockIdx.x;
    int tid = threadIdx.x;

    // ---------------- Phase A: project + bin (4 gaussians per block) -------
    if (tid < 4) {
        int i = b * 4 + tid;   // exactly NG = NB*4

        out[7 * HW + i] = 1.0f;  // opac output = ones(N,1)

        float mx = tanhf(xyz[2 * i + 0]);
        float my = tanhf(xyz[2 * i + 1]);

        float l0 = chol[3 * i + 0] + 0.5f;
        float l1 = chol[3 * i + 1];
        float l2 = chol[3 * i + 2] + 0.5f;

        float s00 = l0 * l0;
        float s01 = l0 * l1;
        float s11 = l1 * l1 + l2 * l2;
        float det = s00 * s11 - s01 * s01;
        float inv = 1.0f / det;
        float c0 =  s11 * inv;
        float c1 = -s01 * inv;
        float c2 =  s00 * inv;

        float px = 0.5f * ((mx + 1.0f) * (float)WIMG - 1.0f);
        float py = 0.5f * ((my + 1.0f) * (float)HIMG - 1.0f);

        float4 pa = make_float4(px, py, 0.5f * c0, c1);
        float4 pb = make_float4(0.5f * c2, feat[3 * i], feat[3 * i + 1], feat[3 * i + 2]);
        float4 pc = make_float4(0.5f * rcol[3 * i], 0.5f * rcol[3 * i + 1],
                                0.5f * rcol[3 * i + 2], 0.0f);

        // Exact extents: live requires sigma <= ln(255) = 5.5413 (+eps).
        const float T = 5.545f;
        float hx = sqrtf(2.0f * T * s00);
        float hy = sqrtf(2.0f * T * s11);

        int x0 = max(0,       (int)ceilf ((px - hx - (float)(TW - 1)) * (1.0f / TW)));
        int x1 = min(TXN - 1, (int)floorf((px + hx) * (1.0f / TW)));
        int y0 = max(0,       (int)ceilf ((py - hy - (float)(TH - 1)) * (1.0f / TH)));
        int y1 = min(TYN - 1, (int)floorf((py + hy) * (1.0f / TH)));

        for (int ty = y0; ty <= y1; ty++) {
            for (int tx = x0; tx <= x1; tx++) {
                int t = ty * TXN + tx;
                int slot = atomicAdd(&g_tile_cnt[t], 1);
                if (slot < CAP) {
                    int p = t * CAP + slot;
                    g_la[p] = pa;
                    g_lb[p] = pb;
                    g_lc[p] = pc;
                }
            }
        }
    }

    // ---------------- Grid barrier: arrive once, poll with plain loads -----
    __threadfence();               // publish phase-A stores before arrival
    __syncthreads();
    if (tid == 0) {
        atomicAdd(&g_arrive, 1);
        volatile int* p = &g_arrive;
        while (*p < NB) __nanosleep(64);
    }
    __syncthreads();
    __threadfence();               // acquire: order phase-B loads after poll

    // ---------------- Phase B: raster 2 tiles (16x8 px) per block ----------
    __shared__ float4 sa[CAP];
    __shared__ float4 sb[CAP];
    __shared__ float4 sc[CAP];

    int lx = tid & (TW - 1);
    int ly = tid >> 4;              // 0..7

    for (int tt = 0; tt < 2; tt++) {
        int tile  = b + tt * NB;
        int tilex = tile & (TXN - 1);
        int tiley = tile >> 5;      // tile / TXN

        int   pxi = tilex * TW + lx;
        int   pyi = tiley * TH + ly;
        float pxf = (float)pxi;
        float pyf = (float)pyi;

        int cnt = min(g_tile_cnt[tile], CAP);

        __syncthreads();            // smem reuse guard (cheap, tt=1 only matters)
        if (tid < cnt) {
            int p = tile * CAP + tid;
            sa[tid] = g_la[p];
            sb[tid] = g_lb[p];
            sc[tid] = g_lc[p];
        }
        __syncthreads();

        float ar = 0.f, ag = 0.f, ab = 0.f;
        float gr = 0.f, gg = 0.f, gb = 0.f;
        float aa = 0.f;

        #pragma unroll 4
        for (int j = 0; j < cnt; j++) {
            float4 a = sa[j];
            float dx = a.x - pxf;
            float dy = a.y - pyf;
            float c2h = sb[j].x;
            float sigma = fmaf(dx, fmaf(a.z, dx, a.w * dy), c2h * dy * dy);
            float e = __expf(-sigma);
            bool live = (sigma >= 0.0f) && (e >= (1.0f / 255.0f));
            float alpha = live ? fminf(0.999f, e) : 0.0f;
            float4 bb = sb[j];
            float4 cc = sc[j];
            ar += alpha * bb.y;
            ag += alpha * bb.z;
            ab += alpha * bb.w;
            gr += alpha * cc.x;
            gg += alpha * cc.y;
            gb += alpha * cc.z;
            aa += alpha;
        }

        int pix = pyi * WIMG + pxi;
        out[0 * HW + pix] = fminf(1.0f, fmaxf(0.0f, ar));
        out[1 * HW + pix] = fminf(1.0f, fmaxf(0.0f, ag));
        out[2 * HW + pix] = fminf(1.0f, fmaxf(0.0f, ab));
        out[3 * HW + pix] = fminf(1.0f, fmaxf(0.0f, gr));
        out[4 * HW + pix] = fminf(1.0f, fmaxf(0.0f, gg));
        out[5 * HW + pix] = fminf(1.0f, fmaxf(0.0f, gb));
        out[6 * HW + pix] = aa;

        if (tid == 0) g_tile_cnt[tile] = 0;   // restore zero state
    }

    // ---------------- Exit: last block resets barrier counters -------------
    __syncthreads();
    if (tid == 0) {
        int d = atomicAdd(&g_done, 1);
        if (d == NB - 1) {
            g_arrive = 0;
            g_done   = 0;
            __threadfence();
        }
    }
}

extern "C" void kernel_launch(void* const* d_in, const int* in_sizes, int n_in,
                              void* d_out, int out_size) {
    const float* xyz  = (const float*)d_in[0];
    const float* chol = (const float*)d_in[1];
    const float* feat = (const float*)d_in[2];
    const float* rcol = (const float*)d_in[3];
    float* out = (float*)d_out;

    fused_kernel<<<NB, NT>>>(xyz, chol, feat, rcol, out);
}

// round 9
// speedup vs baseline: 1.4168x; 1.1317x over previous
#include <cuda_runtime.h>
#include <math.h>

// Problem constants (reference hardcodes H=W=512, N=4096).
#define NG     4096
#define HIMG   512
#define WIMG   512
#define HW     (HIMG * WIMG)
#define TW     16
#define TH     8
#define TXN    (WIMG / TW)     // 32 tiles in x
#define TYN    (HIMG / TH)     // 64 tiles in y
#define NTILES (TXN * TYN)     // 2048
#define CAP    128             // per-tile capacity (observed max ~13-25)
#define NB     1024            // blocks: proven single co-resident wave
#define NT     128             // threads per block

// Static device scratch (zero-initialized at load; kernel restores zeros
// before exit so every graph replay sees identical initial state).
__device__ float4 g_la[NTILES * CAP];       // px, py, 0.5*c0, c1
__device__ float4 g_lb[NTILES * CAP];       // 0.5*c2, feat_r, feat_g, feat_b
__device__ float4 g_lc[NTILES * CAP];       // geo_r, geo_g, geo_b, unused
__device__ int    g_tile_cnt[NTILES];
__device__ int    g_arrive;                 // grid barrier arrive counter
__device__ int    g_done;                   // exit counter (last block resets)

__global__ __launch_bounds__(NT, 8)
void fused_kernel(const float* __restrict__ xyz,
                  const float* __restrict__ chol,
                  const float* __restrict__ feat,
                  const float* __restrict__ rcol,
                  float* __restrict__ out) {
    int b    = blockIdx.x;
    int tid  = threadIdx.x;
    int wid  = tid >> 5;
    int lane = tid & 31;

    // -------- Phase A: one warp per gaussian; one lane per covered tile ----
    {
        int i = b * 4 + wid;   // exactly NG = NB*4 gaussians

        if (lane == 0) out[7 * HW + i] = 1.0f;  // opac output = ones(N,1)

        // All lanes compute the projection redundantly (broadcast loads).
        float mx = tanhf(xyz[2 * i + 0]);
        float my = tanhf(xyz[2 * i + 1]);

        float l0 = chol[3 * i + 0] + 0.5f;
        float l1 = chol[3 * i + 1];
        float l2 = chol[3 * i + 2] + 0.5f;

        float s00 = l0 * l0;
        float s01 = l0 * l1;
        float s11 = l1 * l1 + l2 * l2;
        float det = s00 * s11 - s01 * s01;
        float inv = 1.0f / det;

        float px = 0.5f * ((mx + 1.0f) * (float)WIMG - 1.0f);
        float py = 0.5f * ((my + 1.0f) * (float)HIMG - 1.0f);

        float4 pa = make_float4(px, py, 0.5f * s11 * inv, -s01 * inv);
        float4 pb = make_float4(0.5f * s00 * inv,
                                feat[3 * i], feat[3 * i + 1], feat[3 * i + 2]);
        float4 pc = make_float4(0.5f * rcol[3 * i], 0.5f * rcol[3 * i + 1],
                                0.5f * rcol[3 * i + 2], 0.0f);

        // Exact extents: live requires sigma <= ln(255) = 5.5413 (+eps).
        const float T = 5.545f;
        float hx = sqrtf(2.0f * T * s00);
        float hy = sqrtf(2.0f * T * s11);

        int x0 = max(0,       (int)ceilf ((px - hx - (float)(TW - 1)) * (1.0f / TW)));
        int x1 = min(TXN - 1, (int)floorf((px + hx) * (1.0f / TW)));
        int y0 = max(0,       (int)ceilf ((py - hy - (float)(TH - 1)) * (1.0f / TH)));
        int y1 = min(TYN - 1, (int)floorf((py + hy) * (1.0f / TH)));

        int nx = x1 - x0 + 1;
        int ny = y1 - y0 + 1;
        int nt = (nx > 0 && ny > 0) ? nx * ny : 0;   // <= 12 in practice

        for (int s = lane; s < nt; s += 32) {        // one atomic per lane
            int tx = x0 + (s % nx);
            int ty = y0 + (s / nx);
            int t  = ty * TXN + tx;
            int slot = atomicAdd(&g_tile_cnt[t], 1);
            if (slot < CAP) {
                int p = t * CAP + slot;
                g_la[p] = pa;
                g_lb[p] = pb;
                g_lc[p] = pc;
            }
        }
    }

    // -------- Grid barrier: arrive once, poll with plain loads -------------
    __threadfence();               // publish phase-A stores before arrival
    __syncthreads();
    if (tid == 0) {
        atomicAdd(&g_arrive, 1);
        volatile int* p = &g_arrive;
        while (*p < NB) __nanosleep(64);
    }
    __syncthreads();
    __threadfence();               // acquire: order phase-B loads after poll

    // -------- Phase B: raster 2 tiles (16x8 px), staged together -----------
    __shared__ float4 sa[2][CAP];
    __shared__ float4 sb[2][CAP];
    __shared__ float4 sc[2][CAP];

    int tile0 = b;
    int tile1 = b + NB;

    // Independent loads overlap: both counts, then both payload lists.
    int cnt0 = min(g_tile_cnt[tile0], CAP);
    int cnt1 = min(g_tile_cnt[tile1], CAP);

    if (tid < cnt0) {
        int p = tile0 * CAP + tid;
        sa[0][tid] = g_la[p];
        sb[0][tid] = g_lb[p];
        sc[0][tid] = g_lc[p];
    }
    if (tid < cnt1) {
        int p = tile1 * CAP + tid;
        sa[1][tid] = g_la[p];
        sb[1][tid] = g_lb[p];
        sc[1][tid] = g_lc[p];
    }
    __syncthreads();

    int lx = tid & (TW - 1);
    int ly = tid >> 4;              // 0..7

    #pragma unroll
    for (int tt = 0; tt < 2; tt++) {
        int tile  = (tt == 0) ? tile0 : tile1;
        int cnt   = (tt == 0) ? cnt0  : cnt1;
        int tilex = tile & (TXN - 1);
        int tiley = tile >> 5;      // tile / TXN

        int   pxi = tilex * TW + lx;
        int   pyi = tiley * TH + ly;
        float pxf = (float)pxi;
        float pyf = (float)pyi;

        float ar = 0.f, ag = 0.f, ab = 0.f;
        float gr = 0.f, gg = 0.f, gb = 0.f;
        float aa = 0.f;

        #pragma unroll 4
        for (int j = 0; j < cnt; j++) {
            float4 a = sa[tt][j];
            float dx = a.x - pxf;
            float dy = a.y - pyf;
            float c2h = sb[tt][j].x;
            float sigma = fmaf(dx, fmaf(a.z, dx, a.w * dy), c2h * dy * dy);
            float e = __expf(-sigma);
            bool live = (sigma >= 0.0f) && (e >= (1.0f / 255.0f));
            float alpha = live ? fminf(0.999f, e) : 0.0f;
            float4 bb = sb[tt][j];
            float4 cc = sc[tt][j];
            ar += alpha * bb.y;
            ag += alpha * bb.z;
            ab += alpha * bb.w;
            gr += alpha * cc.x;
            gg += alpha * cc.y;
            gb += alpha * cc.z;
            aa += alpha;
        }

        int pix = pyi * WIMG + pxi;
        out[0 * HW + pix] = fminf(1.0f, fmaxf(0.0f, ar));
        out[1 * HW + pix] = fminf(1.0f, fmaxf(0.0f, ag));
        out[2 * HW + pix] = fminf(1.0f, fmaxf(0.0f, ab));
        out[3 * HW + pix] = fminf(1.0f, fmaxf(0.0f, gr));
        out[4 * HW + pix] = fminf(1.0f, fmaxf(0.0f, gg));
        out[5 * HW + pix] = fminf(1.0f, fmaxf(0.0f, gb));
        out[6 * HW + pix] = aa;

        if (tid == 0) g_tile_cnt[tile] = 0;   // restore zero state
    }

    // -------- Exit: last block resets barrier counters ----------------------
    if (tid == 0) {
        int d = atomicAdd(&g_done, 1);
        if (d == NB - 1) {
            g_arrive = 0;
            g_done   = 0;
            __threadfence();
        }
    }
}

extern "C" void kernel_launch(void* const* d_in, const int* in_sizes, int n_in,
                              void* d_out, int out_size) {
    const float* xyz  = (const float*)d_in[0];
    const float* chol = (const float*)d_in[1];
    const float* feat = (const float*)d_in[2];
    const float* rcol = (const float*)d_in[3];
    float* out = (float*)d_out;

    fused_kernel<<<NB, NT>>>(xyz, chol, feat, rcol, out);
}

// round 11
// speedup vs baseline: 1.6118x; 1.1376x over previous
#include <cuda_runtime.h>
#include <math.h>

// Problem constants (reference hardcodes H=W=512, N=4096).
#define NG     4096
#define HIMG   512
#define WIMG   512
#define HW     (HIMG * WIMG)
#define TW     16
#define TH     8
#define TXN    (WIMG / TW)     // 32 tiles in x
#define TYN    (HIMG / TH)     // 64 tiles in y
#define NTILES (TXN * TYN)     // 2048
#define CAP    128             // per-tile capacity (observed max ~13-25)
#define NB     1024            // blocks: proven single co-resident wave
#define NT     128             // threads per block

// Static device scratch (zero-initialized at load; kernel restores zeros
// before exit so every graph replay sees identical initial state).
__device__ float4 g_la[NTILES * CAP];       // px, py, 0.5*c0, c1
__device__ float4 g_lb[NTILES * CAP];       // 0.5*c2, feat_r, feat_g, feat_b
__device__ float4 g_lc[NTILES * CAP];       // geo_r, geo_g, geo_b, unused
__device__ int    g_tile_cnt[NTILES];
__device__ int    g_arrive;                 // grid barrier arrive counter
__device__ int    g_flag[NB];               // per-block release flags (distributed)
__device__ int    g_done;                   // exit counter (last block resets)

__global__ __launch_bounds__(NT, 8)
void fused_kernel(const float* __restrict__ xyz,
                  const float* __restrict__ chol,
                  const float* __restrict__ feat,
                  const float* __restrict__ rcol,
                  float* __restrict__ out) {
    int b    = blockIdx.x;
    int tid  = threadIdx.x;
    int wid  = tid >> 5;
    int lane = tid & 31;

    __shared__ int s_rel;   // 1 if this block is the barrier releaser

    // -------- Phase A: one warp per gaussian; one lane per covered tile ----
    {
        int i = b * 4 + wid;   // exactly NG = NB*4 gaussians

        if (lane == 0) out[7 * HW + i] = 1.0f;  // opac output = ones(N,1)

        // All lanes compute the projection redundantly (broadcast loads).
        float mx = tanhf(xyz[2 * i + 0]);
        float my = tanhf(xyz[2 * i + 1]);

        float l0 = chol[3 * i + 0] + 0.5f;
        float l1 = chol[3 * i + 1];
        float l2 = chol[3 * i + 2] + 0.5f;

        float s00 = l0 * l0;
        float s01 = l0 * l1;
        float s11 = l1 * l1 + l2 * l2;
        float det = s00 * s11 - s01 * s01;
        float inv = 1.0f / det;

        float px = 0.5f * ((mx + 1.0f) * (float)WIMG - 1.0f);
        float py = 0.5f * ((my + 1.0f) * (float)HIMG - 1.0f);

        float4 pa = make_float4(px, py, 0.5f * s11 * inv, -s01 * inv);
        float4 pb = make_float4(0.5f * s00 * inv,
                                feat[3 * i], feat[3 * i + 1], feat[3 * i + 2]);
        float4 pc = make_float4(0.5f * rcol[3 * i], 0.5f * rcol[3 * i + 1],
                                0.5f * rcol[3 * i + 2], 0.0f);

        // Exact extents: live requires sigma <= ln(255) = 5.5413 (+eps).
        const float T = 5.545f;
        float hx = sqrtf(2.0f * T * s00);
        float hy = sqrtf(2.0f * T * s11);

        int x0 = max(0,       (int)ceilf ((px - hx - (float)(TW - 1)) * (1.0f / TW)));
        int x1 = min(TXN - 1, (int)floorf((px + hx) * (1.0f / TW)));
        int y0 = max(0,       (int)ceilf ((py - hy - (float)(TH - 1)) * (1.0f / TH)));
        int y1 = min(TYN - 1, (int)floorf((py + hy) * (1.0f / TH)));

        int nx = x1 - x0 + 1;
        int ny = y1 - y0 + 1;
        int nt = (nx > 0 && ny > 0) ? nx * ny : 0;   // <= ~12 in practice

        for (int s = lane; s < nt; s += 32) {        // one atomic per lane
            int tx = x0 + (s % nx);
            int ty = y0 + (s / nx);
            int t  = ty * TXN + tx;
            int slot = atomicAdd(&g_tile_cnt[t], 1);
            if (slot < CAP) {
                int p = t * CAP + slot;
                g_la[p] = pa;
                g_lb[p] = pb;
                g_lc[p] = pc;
            }
        }
    }

    // -------- Grid barrier: central arrive, distributed-flag release -------
    // CTA-scope release by all threads, GPU-scope fence by leader only
    // (cooperative-groups grid.sync pattern).
    __syncthreads();
    if (tid == 0) {
        __threadfence();                       // publish phase-A stores
        int old = atomicAdd(&g_arrive, 1);
        s_rel = (old == NB - 1) ? 1 : 0;
    }
    __syncthreads();
    if (s_rel) {
        // Releaser: all 128 threads fan the release out to per-block flags
        // spread across L2 slices (8 stores per thread).
        #pragma unroll
        for (int k = 0; k < NB / NT; k++) {
            *(volatile int*)&g_flag[k * NT + tid] = 1;
        }
    } else if (tid == 0) {
        volatile int* f = &g_flag[b];          // poll OWN flag: no hot address
        while (*f == 0) __nanosleep(128);
        __threadfence();                       // acquire
    }
    __syncthreads();

    // -------- Phase B: raster 2 tiles (16x8 px), staged together -----------
    __shared__ float4 sa[2][CAP];
    __shared__ float4 sb[2][CAP];
    __shared__ float4 sc[2][CAP];

    int tile0 = b;
    int tile1 = b + NB;

    int cnt0 = min(g_tile_cnt[tile0], CAP);
    int cnt1 = min(g_tile_cnt[tile1], CAP);

    if (tid < cnt0) {
        int p = tile0 * CAP + tid;
        sa[0][tid] = g_la[p];
        sb[0][tid] = g_lb[p];
        sc[0][tid] = g_lc[p];
    }
    if (tid < cnt1) {
        int p = tile1 * CAP + tid;
        sa[1][tid] = g_la[p];
        sb[1][tid] = g_lb[p];
        sc[1][tid] = g_lc[p];
    }
    __syncthreads();

    int lx = tid & (TW - 1);
    int ly = tid >> 4;              // 0..7

    #pragma unroll
    for (int tt = 0; tt < 2; tt++) {
        int tile  = (tt == 0) ? tile0 : tile1;
        int cnt   = (tt == 0) ? cnt0  : cnt1;
        int tilex = tile & (TXN - 1);
        int tiley = tile >> 5;      // tile / TXN

        int   pxi = tilex * TW + lx;
        int   pyi = tiley * TH + ly;
        float pxf = (float)pxi;
        float pyf = (float)pyi;

        float ar = 0.f, ag = 0.f, ab = 0.f;
        float gr = 0.f, gg = 0.f, gb = 0.f;
        float aa = 0.f;

        #pragma unroll 4
        for (int j = 0; j < cnt; j++) {
            float4 a = sa[tt][j];
            float dx = a.x - pxf;
            float dy = a.y - pyf;
            float c2h = sb[tt][j].x;
            float sigma = fmaf(dx, fmaf(a.z, dx, a.w * dy), c2h * dy * dy);
            float e = __expf(-sigma);
            bool live = (sigma >= 0.0f) && (e >= (1.0f / 255.0f));
            float alpha = live ? fminf(0.999f, e) : 0.0f;
            float4 bb = sb[tt][j];
            float4 cc = sc[tt][j];
            ar += alpha * bb.y;
            ag += alpha * bb.z;
            ab += alpha * bb.w;
            gr += alpha * cc.x;
            gg += alpha * cc.y;
            gb += alpha * cc.z;
            aa += alpha;
        }

        int pix = pyi * WIMG + pxi;
        out[0 * HW + pix] = fminf(1.0f, fmaxf(0.0f, ar));
        out[1 * HW + pix] = fminf(1.0f, fmaxf(0.0f, ag));
        out[2 * HW + pix] = fminf(1.0f, fmaxf(0.0f, ab));
        out[3 * HW + pix] = fminf(1.0f, fmaxf(0.0f, gr));
        out[4 * HW + pix] = fminf(1.0f, fmaxf(0.0f, gg));
        out[5 * HW + pix] = fminf(1.0f, fmaxf(0.0f, gb));
        out[6 * HW + pix] = aa;

        if (tid == 0) g_tile_cnt[tile] = 0;   // restore zero state
    }

    // -------- Exit: last block out resets barrier state for next replay ----
    __syncthreads();
    if (tid == 0) {
        int d = atomicAdd(&g_done, 1);
        s_rel = (d == NB - 1) ? 1 : 0;
    }
    __syncthreads();
    if (s_rel) {
        #pragma unroll
        for (int k = 0; k < NB / NT; k++) {
            g_flag[k * NT + tid] = 0;
        }
        if (tid == 0) {
            g_arrive = 0;
            g_done   = 0;
            __threadfence();
        }
    }
}

extern "C" void kernel_launch(void* const* d_in, const int* in_sizes, int n_in,
                              void* d_out, int out_size) {
    const float* xyz  = (const float*)d_in[0];
    const float* chol = (const float*)d_in[1];
    const float* feat = (const float*)d_in[2];
    const float* rcol = (const float*)d_in[3];
    float* out = (float*)d_out;

    fused_kernel<<<NB, NT>>>(xyz, chol, feat, rcol, out);
}